// round 7
// baseline (speedup 1.0000x reference)
#include <cuda_runtime.h>
#include <math.h>
#include <stdint.h>

#define NN 50000
#define HD 128
#define EE 600000
#define SCAN_BLOCKS ((NN + 255) / 256)   // 196
#define MB_TILES ((NN + 127) / 128)      // 391
#define CH 32                            // K-chunk

// Scratch (device globals — no allocation allowed in kernel_launch)
__device__ float g_xw [NN * HD];
__device__ float g_h1 [NN * HD];
__device__ float g_h2 [NN * HD];
__device__ float g_wt [4 * HD * HD];     // transposed weights, 4 layers
__device__ float g_dinv[NN];
__device__ int   g_deg [NN];
__device__ int   g_rowptr[NN + 1];
__device__ int   g_head[NN];
__device__ int   g_bsum[SCAN_BLOCKS];
__device__ int   g_boff[SCAN_BLOCKS];
__device__ unsigned long long g_csr[EE];   // [w:f32 | src:i32]

__device__ __forceinline__ float elu(float v) {
    return v > 0.f ? v : expm1f(v);
}

__device__ __forceinline__ uint32_t f2tf32(float v) {
    uint32_t r;
    asm("cvt.rna.tf32.f32 %0, %1;" : "=r"(r) : "f"(v));
    return r;
}

__device__ __forceinline__ void mma_tf32(float& d0, float& d1, float& d2, float& d3,
                                         uint32_t a0, uint32_t a1, uint32_t a2, uint32_t a3,
                                         uint32_t b0, uint32_t b1) {
    asm volatile(
        "mma.sync.aligned.m16n8k8.row.col.f32.tf32.tf32.f32 "
        "{%0,%1,%2,%3}, {%4,%5,%6,%7}, {%8,%9}, {%0,%1,%2,%3};"
        : "+f"(d0), "+f"(d1), "+f"(d2), "+f"(d3)
        : "r"(a0), "r"(a1), "r"(a2), "r"(a3), "r"(b0), "r"(b1));
}

// ---------------------------------------------------------------------------
// Degree / normalization / CSR build
// ---------------------------------------------------------------------------
__global__ void k_zero_deg(int* __restrict__ deg) {
    int i = blockIdx.x * blockDim.x + threadIdx.x;
    if (i < NN) deg[i] = 0;
}

__global__ void k_hist(const int* __restrict__ dst, int* __restrict__ deg) {
    int i = blockIdx.x * blockDim.x + threadIdx.x;
    if (i < EE) atomicAdd(&deg[dst[i]], 1);
}

__global__ void k_blockred(const int* __restrict__ deg, float* __restrict__ dinv) {
    __shared__ int wsum[8];
    int tid = threadIdx.x;
    int i = blockIdx.x * 256 + tid;
    int v = (i < NN) ? deg[i] : 0;
    if (i < NN) dinv[i] = rsqrtf((float)v + 1.0f);

    int x = v;
    #pragma unroll
    for (int off = 16; off; off >>= 1)
        x += __shfl_down_sync(0xffffffffu, x, off);
    if ((tid & 31) == 0) wsum[tid >> 5] = x;
    __syncthreads();
    if (tid < 8) {
        int s = wsum[tid];
        #pragma unroll
        for (int off = 4; off; off >>= 1)
            s += __shfl_down_sync(0xffu, s, off);
        if (tid == 0) g_bsum[blockIdx.x] = s;
    }
}

__global__ void k_scansums() {
    __shared__ int wsum[8];
    int tid = threadIdx.x;
    int lane = tid & 31, wid = tid >> 5;
    int v = (tid < SCAN_BLOCKS) ? g_bsum[tid] : 0;
    int x = v;
    #pragma unroll
    for (int off = 1; off < 32; off <<= 1) {
        int y = __shfl_up_sync(0xffffffffu, x, off);
        if (lane >= off) x += y;
    }
    if (lane == 31) wsum[wid] = x;
    __syncthreads();
    if (wid == 0 && lane < 8) {
        int s = wsum[lane];
        #pragma unroll
        for (int off = 1; off < 8; off <<= 1) {
            int y = __shfl_up_sync(0xffu, s, off);
            if (lane >= off) s += y;
        }
        wsum[lane] = s;
    }
    __syncthreads();
    int excl = x - v + (wid ? wsum[wid - 1] : 0);
    if (tid < SCAN_BLOCKS) g_boff[tid] = excl;
    if (tid == SCAN_BLOCKS - 1) g_rowptr[NN] = excl + v;
}

__global__ void k_scanfinal(const int* __restrict__ deg) {
    __shared__ int wsum[8];
    int tid = threadIdx.x;
    int lane = tid & 31, wid = tid >> 5;
    int i = blockIdx.x * 256 + tid;
    int v = (i < NN) ? deg[i] : 0;
    int x = v;
    #pragma unroll
    for (int off = 1; off < 32; off <<= 1) {
        int y = __shfl_up_sync(0xffffffffu, x, off);
        if (lane >= off) x += y;
    }
    if (lane == 31) wsum[wid] = x;
    __syncthreads();
    if (wid == 0 && lane < 8) {
        int s = wsum[lane];
        #pragma unroll
        for (int off = 1; off < 8; off <<= 1) {
            int y = __shfl_up_sync(0xffu, s, off);
            if (lane >= off) s += y;
        }
        wsum[lane] = s;
    }
    __syncthreads();
    int excl = x - v + (wid ? wsum[wid - 1] : 0) + g_boff[blockIdx.x];
    if (i < NN) { g_rowptr[i] = excl; g_head[i] = excl; }
}

__global__ void k_fill(const int* __restrict__ src, const int* __restrict__ dst,
                       const float* __restrict__ dinv) {
    int e = blockIdx.x * blockDim.x + threadIdx.x;
    if (e >= EE) return;
    int s = src[e];
    int d = dst[e];
    float w = dinv[s] * dinv[d];
    int pos = atomicAdd(&g_head[d], 1);
    g_csr[pos] = ((unsigned long long)__float_as_uint(w) << 32) | (unsigned)s;
}

// ---------------------------------------------------------------------------
// Transpose all 4 weight matrices: Wt[l][n][k] = W[l][k][n]
// ---------------------------------------------------------------------------
__global__ void k_wt4(const float* __restrict__ W0, const float* __restrict__ W1,
                      const float* __restrict__ W2, const float* __restrict__ W3) {
    const float* Ws[4] = {W0, W1, W2, W3};
    int i = blockIdx.x * 256 + threadIdx.x;   // grid 256 -> 65536 elems
    int l = i >> 14;
    int r = i & 16383;
    int k = r >> 7;
    int n = r & 127;
    g_wt[l * HD * HD + n * HD + k] = Ws[l][k * HD + n];
}

// ---------------------------------------------------------------------------
// Tensor-core GEMM via mma.sync tf32 (3xTF32 split -> fp32-grade accuracy).
// CTA: 128(M) x 64(N); grid (MB_TILES, 2). 8 warps in 4x2; warp tile 32x32.
// K chunked by 32. Fragments staged in FRAGMENT-MAJOR smem:
//   index = (tile*32 + lane)*nregs + reg,  lane = (rowInTile&7)*4 + (k&3)
// so each A frag is one LDS.128 and each B frag one LDS.64.
// ---------------------------------------------------------------------------
__global__ __launch_bounds__(256) void k_gemm_mma(
    const float* __restrict__ X, const float* __restrict__ Wt,
    float* __restrict__ XW)
{
    // frag-major layouts:
    //  A: [mtile(8)*ktile(4)][lane(32)][reg(4)]  = 4096 u32
    //  B: [ntile(8)*ktile(4)][lane(32)][reg(2)]  = 2048 u32
    __shared__ uint32_t AH[4096], AL[4096], BH[2048], BL[2048];

    const int tid = threadIdx.x;
    const int wid = tid >> 5;
    const int lane = tid & 31;
    const int warpM = wid & 3;        // 0..3 -> rows 32*warpM
    const int warpN = wid >> 2;       // 0..1 -> cols 32*warpN
    const int blockRow = blockIdx.x * 128;
    const int nOff = blockIdx.y * 64;

    float acc[2][4][4] = {};

    for (int c = 0; c < 4; c++) {
        const int k0 = c * CH;

        // ---- load + split + frag-major store: A (128x32) ----
        #pragma unroll
        for (int i = 0; i < 4; i++) {
            int lin = tid + i * 256;          // 1024 float4 slots
            int r   = lin >> 3;               // 0..127
            int c4  = lin & 7;                // 0..7 (col group of 4)
            float4 v = make_float4(0.f, 0.f, 0.f, 0.f);
            if (blockRow + r < NN)
                v = *(const float4*)(X + (size_t)(blockRow + r) * HD + k0 + c4 * 4);
            int mt = r >> 4, kt = c4 >> 1;
            int jb = (c4 & 1) * 2 + ((r >> 3) & 1);   // reg = colHalf*2 + rowHalf
            int base = ((mt * 4 + kt) * 32 + (r & 7) * 4) * 4 + jb;
            float va[4] = {v.x, v.y, v.z, v.w};
            #pragma unroll
            for (int e = 0; e < 4; e++) {             // lane += e  ->  +e*4
                uint32_t h = f2tf32(va[e]);
                AH[base + e * 4] = h;
                AL[base + e * 4] = f2tf32(va[e] - __uint_as_float(h));
            }
        }
        // ---- load + split + frag-major store: B (64x32) ----
        #pragma unroll
        for (int i = 0; i < 2; i++) {
            int lin = tid + i * 256;          // 512 float4 slots
            int n   = lin >> 3;               // 0..63
            int c4  = lin & 7;
            float4 v = *(const float4*)(Wt + (size_t)(nOff + n) * HD + k0 + c4 * 4);
            int nt = n >> 3, kt = c4 >> 1;
            int jb = (c4 & 1);                        // reg = k>>2 within tile
            int base = ((nt * 4 + kt) * 32 + (n & 7) * 4) * 2 + jb;
            float vb[4] = {v.x, v.y, v.z, v.w};
            #pragma unroll
            for (int e = 0; e < 4; e++) {             // lane += e  ->  +e*2
                uint32_t h = f2tf32(vb[e]);
                BH[base + e * 2] = h;
                BL[base + e * 2] = f2tf32(vb[e] - __uint_as_float(h));
            }
        }
        __syncthreads();

        // ---- MMA: 4 k8-steps per chunk ----
        #pragma unroll
        for (int kt = 0; kt < 4; kt++) {
            uint4 ah[2], al[2];
            #pragma unroll
            for (int mt = 0; mt < 2; mt++) {
                int idx = (((warpM * 2 + mt) * 4 + kt) * 32 + lane) * 4;
                ah[mt] = *(const uint4*)(AH + idx);
                al[mt] = *(const uint4*)(AL + idx);
            }
            #pragma unroll
            for (int nt = 0; nt < 4; nt++) {
                int idx = (((warpN * 4 + nt) * 4 + kt) * 32 + lane) * 2;
                uint2 bh = *(const uint2*)(BH + idx);
                uint2 bl = *(const uint2*)(BL + idx);
                #pragma unroll
                for (int mt = 0; mt < 2; mt++) {
                    float* d = acc[mt][nt];
                    mma_tf32(d[0], d[1], d[2], d[3],
                             al[mt].x, al[mt].y, al[mt].z, al[mt].w, bh.x, bh.y);
                    mma_tf32(d[0], d[1], d[2], d[3],
                             ah[mt].x, ah[mt].y, ah[mt].z, ah[mt].w, bl.x, bl.y);
                    mma_tf32(d[0], d[1], d[2], d[3],
                             ah[mt].x, ah[mt].y, ah[mt].z, ah[mt].w, bh.x, bh.y);
                }
            }
        }
        __syncthreads();
    }

    // ---- epilogue: direct STG.64 (c0,c1 adjacent cols; c2,c3 row+8) ----
    #pragma unroll
    for (int mt = 0; mt < 2; mt++) {
        int row0 = blockRow + warpM * 32 + mt * 16 + (lane >> 2);
        #pragma unroll
        for (int nt = 0; nt < 4; nt++) {
            int col = nOff + warpN * 32 + nt * 8 + (lane & 3) * 2;
            if (row0 < NN)
                *(float2*)(XW + (size_t)row0 * HD + col) =
                    make_float2(acc[mt][nt][0], acc[mt][nt][1]);
            if (row0 + 8 < NN)
                *(float2*)(XW + (size_t)(row0 + 8) * HD + col) =
                    make_float2(acc[mt][nt][2], acc[mt][nt][3]);
        }
    }
}

// ---------------------------------------------------------------------------
// CSR gather + self-loop + bias + ELU fused. One warp per dst node.
// ---------------------------------------------------------------------------
__global__ __launch_bounds__(256) void k_gather(
    const float* __restrict__ XW, const float* __restrict__ dinv,
    const float* __restrict__ bias, float* __restrict__ H)
{
    int gt   = blockIdx.x * blockDim.x + threadIdx.x;
    int node = gt >> 5;
    int lane = gt & 31;
    if (node >= NN) return;

    int beg = g_rowptr[node];
    int end = g_rowptr[node + 1];
    float d  = dinv[node];
    float d2 = d * d;

    float4 acc = *(const float4*)(XW + (size_t)node * HD + lane * 4);
    acc.x *= d2; acc.y *= d2; acc.z *= d2; acc.w *= d2;

    for (int j = beg; j < end; j++) {
        unsigned long long pv = g_csr[j];
        int   s = (int)(unsigned)(pv & 0xffffffffu);
        float w = __uint_as_float((unsigned)(pv >> 32));
        float4 v = *(const float4*)(XW + (size_t)s * HD + lane * 4);
        acc.x = fmaf(w, v.x, acc.x);
        acc.y = fmaf(w, v.y, acc.y);
        acc.z = fmaf(w, v.z, acc.z);
        acc.w = fmaf(w, v.w, acc.w);
    }

    float4 bb = *(const float4*)(bias + lane * 4);
    float4 r;
    r.x = elu(acc.x + bb.x);
    r.y = elu(acc.y + bb.y);
    r.z = elu(acc.z + bb.z);
    r.w = elu(acc.w + bb.w);
    *(float4*)(H + (size_t)node * HD + lane * 4) = r;
}

// ---------------------------------------------------------------------------
// Output head: S = elu(h @ Wm2 + bm2) (N x 10). Warp per row.
// (Wm1/bm1 are dead code in the reference.)
// ---------------------------------------------------------------------------
__global__ __launch_bounds__(256) void k_mlp(
    const float* __restrict__ Hin, const float* __restrict__ Wm,
    const float* __restrict__ bm, float* __restrict__ S)
{
    __shared__ float Ws[HD * 10];
    __shared__ float bs[10];
    int tid = threadIdx.x;
    for (int i = tid; i < HD * 10; i += 256) Ws[i] = Wm[i];
    if (tid < 10) bs[tid] = bm[tid];
    __syncthreads();

    int warp = tid >> 5, lane = tid & 31;
    int row = blockIdx.x * 8 + warp;
    if (row >= NN) return;

    float acc[10] = {};
    #pragma unroll
    for (int kk = 0; kk < 4; kk++) {
        int k = kk * 32 + lane;
        float hv = Hin[(size_t)row * HD + k];
        #pragma unroll
        for (int c = 0; c < 10; c++) acc[c] += hv * Ws[k * 10 + c];
    }
    #pragma unroll
    for (int c = 0; c < 10; c++) {
        #pragma unroll
        for (int off = 16; off; off >>= 1)
            acc[c] += __shfl_down_sync(0xffffffffu, acc[c], off);
    }
    if (lane == 0) {
        #pragma unroll
        for (int c = 0; c < 10; c++) {
            float v = acc[c] + bs[c];
            S[(size_t)row * 10 + c] = elu(v);
        }
    }
}

// ---------------------------------------------------------------------------
extern "C" void kernel_launch(void* const* d_in, const int* in_sizes, int n_in,
                              void* d_out, int out_size)
{
    const float* x   = (const float*)d_in[0];
    const int*   ei  = (const int*)d_in[1];
    const int*   src = ei;
    const int*   dst = ei + EE;
    const float* W[4] = {(const float*)d_in[2], (const float*)d_in[4],
                         (const float*)d_in[6], (const float*)d_in[8]};
    const float* b[4] = {(const float*)d_in[3], (const float*)d_in[5],
                         (const float*)d_in[7], (const float*)d_in[9]};
    const float* Wm2 = (const float*)d_in[12];
    const float* bm2 = (const float*)d_in[13];

    float* out_h = (float*)d_out;                 // [NN, 128]
    float* out_S = out_h + (size_t)NN * HD;       // [NN, 10]

    float *xw, *h1, *h2, *dinv, *wt;
    int* deg;
    cudaGetSymbolAddress((void**)&xw,   g_xw);
    cudaGetSymbolAddress((void**)&h1,   g_h1);
    cudaGetSymbolAddress((void**)&h2,   g_h2);
    cudaGetSymbolAddress((void**)&dinv, g_dinv);
    cudaGetSymbolAddress((void**)&wt,   g_wt);
    cudaGetSymbolAddress((void**)&deg,  g_deg);

    // Degree, normalization, CSR build, weight transpose (once per launch)
    k_zero_deg<<<(NN + 255) / 256, 256>>>(deg);
    k_hist<<<(EE + 255) / 256, 256>>>(dst, deg);
    k_blockred<<<SCAN_BLOCKS, 256>>>(deg, dinv);
    k_scansums<<<1, 256>>>();
    k_scanfinal<<<SCAN_BLOCKS, 256>>>(deg);
    k_fill<<<(EE + 255) / 256, 256>>>(src, dst, dinv);
    k_wt4<<<256, 256>>>(W[0], W[1], W[2], W[3]);

    const int gather_blocks = (NN * 32 + 255) / 256;      // 6250
    dim3 gemm_grid(MB_TILES, 2);

    const float* in = x;
    float* houts[4] = {h1, h2, h1, out_h};
    for (int l = 0; l < 4; l++) {
        k_gemm_mma<<<gemm_grid, 256>>>(in, wt + (size_t)l * HD * HD, xw);
        k_gather<<<gather_blocks, 256>>>(xw, dinv, b[l], houts[l]);
        in = houts[l];
    }

    k_mlp<<<(NN + 7) / 8, 256>>>(out_h, Wm2, bm2, out_S);
}